// round 12
// baseline (speedup 1.0000x reference)
#include <cuda_runtime.h>
#include <cuda_fp16.h>
#include <math.h>

// ---------------------------------------------------------------------------
// Repacked texture scratch: all 6 spec mips + diffuse map as float4 texels.
// Spec texel counts: 1572864, 393216, 98304, 24576, 6144, 1536 (total 2096640).
// Offsets: 0, 1572864, 1966080, 2064384, 2088960, 2095104. Diffuse at DIFF_OFF.
// ---------------------------------------------------------------------------
#define SPEC_TOTAL 2096640
#define DIFF_OFF   SPEC_TOTAL
#define TEX_TOTAL  (SPEC_TOTAL + 1536)
#define MIP4_OFF   2088960
#define MIP5_OFF   2095104
__device__ float4 g_tex[TEX_TOTAL];

__constant__ int c_spec_off[6] = {0, 1572864, 1966080, 2064384, 2088960, 2095104};
__constant__ int c_spec_res[6] = {512, 256, 128, 64, 32, 16};

__global__ void repack_all_kernel(
    const float* __restrict__ s0, const float* __restrict__ s1,
    const float* __restrict__ s2, const float* __restrict__ s3,
    const float* __restrict__ s4, const float* __restrict__ s5,
    const float* __restrict__ dm)
{
    int i = blockIdx.x * blockDim.x + threadIdx.x;
    if (i >= TEX_TOTAL) return;
    const float* src; int local;
    if (i < 1572864)      { src = s0; local = i; }
    else if (i < 1966080) { src = s1; local = i - 1572864; }
    else if (i < 2064384) { src = s2; local = i - 1966080; }
    else if (i < 2088960) { src = s3; local = i - 2064384; }
    else if (i < 2095104) { src = s4; local = i - 2088960; }
    else if (i < 2096640) { src = s5; local = i - 2095104; }
    else                  { src = dm; local = i - 2096640; }
    const float* p = src + 3 * (size_t)local;
    g_tex[i] = make_float4(p[0], p[1], p[2], 0.f);
}

struct F3 { float x, y, z; };
__device__ __forceinline__ F3 f3(float a, float b, float c) { F3 r; r.x=a; r.y=b; r.z=c; return r; }

struct CubeUV { int face; float u, v; };

__device__ __forceinline__ CubeUV cube_face_uv(F3 d) {
    float ax = fabsf(d.x), ay = fabsf(d.y), az = fabsf(d.z);
    bool is_x = (ax >= ay) && (ax >= az);
    bool is_y = (!is_x) && (ay >= az);
    CubeUV r;
    float ma;
    if (is_x) {
        r.face = (d.x > 0.f) ? 0 : 1;
        ma = ax;
        r.u = (d.x > 0.f) ? -d.z : d.z;
        r.v = -d.y;
    } else if (is_y) {
        r.face = (d.y > 0.f) ? 2 : 3;
        ma = ay;
        r.u = d.x;
        r.v = (d.y > 0.f) ? d.z : -d.z;
    } else {
        r.face = (d.z > 0.f) ? 4 : 5;
        ma = az;
        r.u = d.x * ((d.z > 0.f) ? 1.f : -1.f);
        r.v = -d.y;
    }
    float inv_ma = 1.f / fmaxf(ma, 1e-20f);
    r.u *= inv_ma; r.v *= inv_ma;
    return r;
}

struct BilinIdx { int i00, i01, i10, i11; float w00, w01, w10, w11; };

__device__ __forceinline__ BilinIdx bilin_idx(int R, CubeUV cu) {
    float fu = fmaf(cu.u, 0.5f * (float)R, 0.5f * (float)R - 0.5f);
    float fv = fmaf(cu.v, 0.5f * (float)R, 0.5f * (float)R - 0.5f);
    float x0f = floorf(fu), y0f = floorf(fv);
    float tx = fu - x0f, ty = fv - y0f;
    int x0 = min(max((int)x0f, 0), R - 1);
    int x1 = min(x0 + 1, R - 1);
    int y0 = min(max((int)y0f, 0), R - 1);
    int y1 = min(y0 + 1, R - 1);
    int base = cu.face * R * R;
    BilinIdx b;
    b.i00 = base + y0 * R + x0;
    b.i01 = base + y0 * R + x1;
    b.i10 = base + y1 * R + x0;
    b.i11 = base + y1 * R + x1;
    b.w00 = (1.f - tx) * (1.f - ty);
    b.w01 = tx * (1.f - ty);
    b.w10 = (1.f - tx) * ty;
    b.w11 = tx * ty;
    return b;
}

__device__ __forceinline__ F3 blend4(float4 c00, float4 c01, float4 c10, float4 c11, BilinIdx b) {
    return f3(c00.x*b.w00 + c01.x*b.w01 + c10.x*b.w10 + c11.x*b.w11,
              c00.y*b.w00 + c01.y*b.w01 + c10.y*b.w10 + c11.y*b.w11,
              c00.z*b.w00 + c01.z*b.w01 + c10.z*b.w10 + c11.z*b.w11);
}

__device__ __forceinline__ F3 bilerp_global(int off, int R, CubeUV cu) {
    BilinIdx b = bilin_idx(R, cu);
    const float4* t = g_tex + off;
    return blend4(__ldg(t + b.i00), __ldg(t + b.i01), __ldg(t + b.i10), __ldg(t + b.i11), b);
}

__device__ __forceinline__ float4 h4_to_f4(ushort4 u) {
    return make_float4(__half2float(__ushort_as_half(u.x)),
                       __half2float(__ushort_as_half(u.y)),
                       __half2float(__ushort_as_half(u.z)), 0.f);
}

__device__ __forceinline__ F3 bilerp_smem_h4(const ushort4* __restrict__ s, int R, CubeUV cu) {
    BilinIdx b = bilin_idx(R, cu);
    return blend4(h4_to_f4(s[b.i00]), h4_to_f4(s[b.i01]),
                  h4_to_f4(s[b.i10]), h4_to_f4(s[b.i11]), b);
}

__device__ __forceinline__ F3 sample_spec_level(int l, CubeUV cu,
                                                const ushort4* __restrict__ s_mip5,
                                                const ushort4* __restrict__ s_mip4) {
    if (l <= 3) return bilerp_global(c_spec_off[l], c_spec_res[l], cu);
    if (l == 4) return bilerp_smem_h4(s_mip4, 32, cu);
    return bilerp_smem_h4(s_mip5, 16, cu);
}

__device__ __forceinline__ float srgb1(float x) {
    float lin = 12.92f * x;
    float xa = fmaxf(x, 0.0031308f);
    float g = 1.055f * exp2f(__log2f(xa) * (1.0f / 2.4f)) - 0.055f;
    return (x <= 0.0031308f) ? lin : g;
}

__device__ __forceinline__ ushort4 f4_to_h4(float4 v) {
    return make_ushort4(__half_as_ushort(__float2half_rn(v.x)),
                        __half_as_ushort(__float2half_rn(v.y)),
                        __half_as_ushort(__float2half_rn(v.z)), 0);
}

#define THREADS 192
#define BLOCKS_PER_SM 3
#define GRIDB   456   // 3 blocks per SM on GB300 (152 SMs)

__global__ __launch_bounds__(THREADS, BLOCKS_PER_SM)
void envlight_kernel(
    const float* __restrict__ view_dir,
    const float* __restrict__ normal,
    const float* __restrict__ kd,
    const float* __restrict__ ks,
    const float* __restrict__ reflect_occ,
    const float* __restrict__ fg_lut,
    float* __restrict__ out,
    int ngroups)
{
    extern __shared__ unsigned char smem_raw[];
    ushort4* s_diff = (ushort4*)smem_raw;                // 1536 * 8B = 12KB
    ushort4* s_mip5 = s_diff + 1536;                     // 1536 * 8B = 12KB
    ushort4* s_mip4 = s_mip5 + 1536;                     // 6144 * 8B = 48KB

    for (int i = threadIdx.x; i < 1536; i += THREADS) {
        s_diff[i] = f4_to_h4(g_tex[DIFF_OFF + i]);
        s_mip5[i] = f4_to_h4(g_tex[MIP5_OFF + i]);
    }
    for (int i = threadIdx.x; i < 6144; i += THREADS) {
        s_mip4[i] = f4_to_h4(g_tex[MIP4_OFF + i]);
    }
    __syncthreads();

    // 4 points per thread (ILP for gather latency hiding), persistent grid-stride.
    for (int t = blockIdx.x * THREADS + threadIdx.x; t < ngroups; t += GRIDB * THREADS) {
        const float4* v4  = (const float4*)view_dir   + 3 * (size_t)t;
        const float4* n4  = (const float4*)normal     + 3 * (size_t)t;
        const float4* kd4 = (const float4*)kd         + 3 * (size_t)t;
        const float4* ks4 = (const float4*)ks         + 3 * (size_t)t;

        float vv[12], nn[12], dd[12], ss[12], oo[12];
        {
            float4 a = __ldg(v4), b = __ldg(v4 + 1), c = __ldg(v4 + 2);
            vv[0]=a.x; vv[1]=a.y; vv[2]=a.z; vv[3]=a.w; vv[4]=b.x; vv[5]=b.y;
            vv[6]=b.z; vv[7]=b.w; vv[8]=c.x; vv[9]=c.y; vv[10]=c.z; vv[11]=c.w;
        }
        {
            float4 a = __ldg(n4), b = __ldg(n4 + 1), c = __ldg(n4 + 2);
            nn[0]=a.x; nn[1]=a.y; nn[2]=a.z; nn[3]=a.w; nn[4]=b.x; nn[5]=b.y;
            nn[6]=b.z; nn[7]=b.w; nn[8]=c.x; nn[9]=c.y; nn[10]=c.z; nn[11]=c.w;
        }
        {
            float4 a = __ldg(kd4), b = __ldg(kd4 + 1), c = __ldg(kd4 + 2);
            dd[0]=a.x; dd[1]=a.y; dd[2]=a.z; dd[3]=a.w; dd[4]=b.x; dd[5]=b.y;
            dd[6]=b.z; dd[7]=b.w; dd[8]=c.x; dd[9]=c.y; dd[10]=c.z; dd[11]=c.w;
        }
        {
            float4 a = __ldg(ks4), b = __ldg(ks4 + 1), c = __ldg(ks4 + 2);
            ss[0]=a.x; ss[1]=a.y; ss[2]=a.z; ss[3]=a.w; ss[4]=b.x; ss[5]=b.y;
            ss[6]=b.z; ss[7]=b.w; ss[8]=c.x; ss[9]=c.y; ss[10]=c.z; ss[11]=c.w;
        }
        float4 occ4 = __ldg((const float4*)reflect_occ + t);
        float occA[4] = {occ4.x, occ4.y, occ4.z, occ4.w};

        #pragma unroll
        for (int p = 0; p < 4; p++) {
            F3 v   = f3(vv[3*p], vv[3*p+1], vv[3*p+2]);
            F3 nrm = f3(nn[3*p], nn[3*p+1], nn[3*p+2]);
            F3 kdv = f3(dd[3*p], dd[3*p+1], dd[3*p+2]);
            float ks0 = ss[3*p], roughness = ss[3*p+1], metallic = ss[3*p+2];
            float occ = occA[p];

            F3 spec_col = f3((1.f - metallic) * 0.04f + kdv.x * metallic,
                             (1.f - metallic) * 0.04f + kdv.y * metallic,
                             (1.f - metallic) * 0.04f + kdv.z * metallic);
            F3 diff_col = f3(kdv.x * (1.f - metallic), kdv.y * (1.f - metallic), kdv.z * (1.f - metallic));

            float vdotn = v.x * nrm.x + v.y * nrm.y + v.z * nrm.z;
            F3 refl = f3(2.f * vdotn * nrm.x - v.x,
                         2.f * vdotn * nrm.y - v.y,
                         2.f * vdotn * nrm.z - v.z);
            float rr = fmaxf(refl.x*refl.x + refl.y*refl.y + refl.z*refl.z, 1e-20f);
            float rinv = rsqrtf(rr);
            refl = f3(refl.x * rinv, refl.y * rinv, refl.z * rinv);

            // diffuse from smem 16^2 cubemap (half texels)
            CubeUV cun = cube_face_uv(nrm);
            F3 diffuse = bilerp_smem_h4(s_diff, 16, cun);
            diffuse = f3(fmaxf(diffuse.x, 0.f), fmaxf(diffuse.y, 0.f), fmaxf(diffuse.z, 0.f));
            float kdocc = 1.f - ks0;
            F3 shaded = f3(diffuse.x * diff_col.x * kdocc,
                           diffuse.y * diff_col.y * kdocc,
                           diffuse.z * diff_col.z * kdocc);

            // FG LUT 256x256x2 via float2 loads (global, L2-resident)
            float NdotV = fmaxf(vdotn, 0.0001f);
            float fg0, fg1;
            {
                const int W = 256, H = 256;
                float fx = NdotV * W - 0.5f;
                float fy = roughness * H - 0.5f;
                float x0f = floorf(fx), y0f = floorf(fy);
                float tx = fx - x0f, ty = fy - y0f;
                int x0 = min(max((int)x0f, 0), W - 1);
                int x1 = min(x0 + 1, W - 1);
                int y0 = min(max((int)y0f, 0), H - 1);
                int y1 = min(y0 + 1, H - 1);
                const float2* L = (const float2*)fg_lut;
                float2 c00 = __ldg(L + y0 * W + x0);
                float2 c01 = __ldg(L + y0 * W + x1);
                float2 c10 = __ldg(L + y1 * W + x0);
                float2 c11 = __ldg(L + y1 * W + x1);
                float w00 = (1.f - tx) * (1.f - ty);
                float w01 = tx * (1.f - ty);
                float w10 = (1.f - tx) * ty;
                float w11 = tx * ty;
                fg0 = c00.x*w00 + c01.x*w01 + c10.x*w10 + c11.x*w11;
                fg1 = c00.y*w00 + c01.y*w01 + c10.y*w10 + c11.y*w11;
            }

            // mip level selection
            const float MIN_R = 0.08f, MAX_R = 0.5f;
            const int L = 6;
            float rc_lo = fminf(fmaxf(roughness, MIN_R), MAX_R);
            float lo = (rc_lo - MIN_R) * ((float)(L - 2) / (MAX_R - MIN_R));
            float rc_hi = fminf(fmaxf(roughness, MAX_R), 1.0f);
            float hi = (rc_hi - MAX_R) * (1.0f / (1.0f - MAX_R)) + (float)(L - 2);
            float lvl = (roughness < MAX_R) ? lo : hi;
            lvl = fminf(fmaxf(lvl, 0.f), (float)(L - 1));
            int l0 = (int)floorf(lvl);
            int l1 = min(l0 + 1, L - 1);
            float lf = lvl - (float)l0;

            CubeUV cur = cube_face_uv(refl);
            F3 s0 = sample_spec_level(l0, cur, s_mip5, s_mip4);
            F3 s1 = sample_spec_level(l1, cur, s_mip5, s_mip4);
            F3 spec = f3(s0.x * (1.f - lf) + s1.x * lf,
                         s0.y * (1.f - lf) + s1.y * lf,
                         s0.z * (1.f - lf) + s1.z * lf);
            spec = f3(fmaxf(spec.x, 0.f), fmaxf(spec.y, 0.f), fmaxf(spec.z, 0.f));

            float so = 1.f - occ;
            float rx = spec_col.x * fg0 + fg1;
            float ry = spec_col.y * fg0 + fg1;
            float rz = spec_col.z * fg0 + fg1;
            oo[3*p]   = srgb1(fminf(fmaxf(shaded.x + spec.x * rx * so, 0.f), 1.f));
            oo[3*p+1] = srgb1(fminf(fmaxf(shaded.y + spec.y * ry * so, 0.f), 1.f));
            oo[3*p+2] = srgb1(fminf(fmaxf(shaded.z + spec.z * rz * so, 0.f), 1.f));
        }

        float4* o4 = (float4*)out + 3 * (size_t)t;
        o4[0] = make_float4(oo[0], oo[1], oo[2], oo[3]);
        o4[1] = make_float4(oo[4], oo[5], oo[6], oo[7]);
        o4[2] = make_float4(oo[8], oo[9], oo[10], oo[11]);
    }
}

#define SMEM_BYTES (1536*8 + 1536*8 + 6144*8)   // 72 KB

extern "C" void kernel_launch(void* const* d_in, const int* in_sizes, int n_in,
                              void* d_out, int out_size) {
    const float* view_dir    = (const float*)d_in[0];
    const float* normal      = (const float*)d_in[1];
    const float* kd          = (const float*)d_in[2];
    const float* ks          = (const float*)d_in[3];
    const float* reflect_occ = (const float*)d_in[4];
    const float* diffuse_map = (const float*)d_in[5];
    const float* fg_lut      = (const float*)d_in[12];
    float* out = (float*)d_out;

    cudaFuncSetAttribute(envlight_kernel,
                         cudaFuncAttributeMaxDynamicSharedMemorySize, SMEM_BYTES);

    // One fused repack launch for all mips + diffuse
    {
        int threads = 256;
        int blocks = (TEX_TOTAL + threads - 1) / threads;
        repack_all_kernel<<<blocks, threads>>>(
            (const float*)d_in[6], (const float*)d_in[7], (const float*)d_in[8],
            (const float*)d_in[9], (const float*)d_in[10], (const float*)d_in[11],
            diffuse_map);
    }

    int n = in_sizes[0] / 3;          // 2,097,152 (divisible by 4)
    int ngroups = n / 4;
    envlight_kernel<<<GRIDB, THREADS, SMEM_BYTES>>>(view_dir, normal, kd, ks, reflect_occ,
                                                    fg_lut, out, ngroups);
}

// round 13
// speedup vs baseline: 1.3503x; 1.3503x over previous
#include <cuda_runtime.h>
#include <cuda_fp16.h>
#include <math.h>

// ---------------------------------------------------------------------------
// Texture storage:
//  - Spec mips 0-3 as half4 texels in DUAL-COPY pair layout:
//      g_mipA: texel array (pairs at even texel index are 16B-aligned)
//      g_mipB: same array shifted by one texel (pairs at odd starts aligned)
//    One LDG.128 fetches both bilinear row-corners (c00,c01) or (c10,c11).
//  - FG LUT as half2 texels in the same dual-copy layout (uint2 pair loads).
//  - Mip4, mip5, diffuse as float4 in g_small -> copied to smem per block.
// Mips 0-3 texel counts: 1572864, 393216, 98304, 24576 (total 2088960).
// Offsets: 0, 1572864, 1966080, 2064384.
// ---------------------------------------------------------------------------
#define NMIP03 2088960
#define NSMALL 9216      // mip4 (6144) + mip5 (1536) + diffuse (1536)
#define NLUT   65536     // 256 x 256
#define NREPACK (NMIP03 + NSMALL + NLUT)

__device__ uint4  g_mipA[NMIP03/2 + 2];   // half4 texel pairs, even starts
__device__ uint4  g_mipB[NMIP03/2 + 2];   // shifted by one texel
__device__ float4 g_small[NSMALL];
__device__ uint2  g_lutA[NLUT/2 + 2];     // half2 texel pairs, even starts
__device__ uint2  g_lutB[NLUT/2 + 2];     // shifted by one texel

__constant__ int c_spec_off[4] = {0, 1572864, 1966080, 2064384};
__constant__ int c_spec_res[6] = {512, 256, 128, 64, 32, 16};

__global__ void repack_all_kernel(
    const float* __restrict__ s0, const float* __restrict__ s1,
    const float* __restrict__ s2, const float* __restrict__ s3,
    const float* __restrict__ s4, const float* __restrict__ s5,
    const float* __restrict__ dm, const float* __restrict__ lut)
{
    int i = blockIdx.x * blockDim.x + threadIdx.x;
    if (i >= NREPACK) return;
    if (i < NMIP03) {
        const float* src; int local;
        if (i < 1572864)      { src = s0; local = i; }
        else if (i < 1966080) { src = s1; local = i - 1572864; }
        else if (i < 2064384) { src = s2; local = i - 1966080; }
        else                  { src = s3; local = i - 2064384; }
        const float* p = src + 3 * (size_t)local;
        ushort4 v = make_ushort4(__half_as_ushort(__float2half_rn(p[0])),
                                 __half_as_ushort(__float2half_rn(p[1])),
                                 __half_as_ushort(__float2half_rn(p[2])), 0);
        ((ushort4*)g_mipA)[i] = v;
        if (i > 0) ((ushort4*)g_mipB)[i - 1] = v;
    } else if (i < NMIP03 + NSMALL) {
        int j = i - NMIP03;
        const float* src; int local;
        if (j < 6144)      { src = s4; local = j; }
        else if (j < 7680) { src = s5; local = j - 6144; }
        else               { src = dm; local = j - 7680; }
        const float* p = src + 3 * (size_t)local;
        g_small[j] = make_float4(p[0], p[1], p[2], 0.f);
    } else {
        int j = i - NMIP03 - NSMALL;
        __half2 h = __floats2half2_rn(lut[2 * (size_t)j], lut[2 * (size_t)j + 1]);
        ((__half2*)g_lutA)[j] = h;
        if (j > 0) ((__half2*)g_lutB)[j - 1] = h;
    }
}

struct F3 { float x, y, z; };
__device__ __forceinline__ F3 f3(float a, float b, float c) { F3 r; r.x=a; r.y=b; r.z=c; return r; }

struct CubeUV { int face; float u, v; };

__device__ __forceinline__ CubeUV cube_face_uv(F3 d) {
    float ax = fabsf(d.x), ay = fabsf(d.y), az = fabsf(d.z);
    bool is_x = (ax >= ay) && (ax >= az);
    bool is_y = (!is_x) && (ay >= az);
    CubeUV r;
    float ma;
    if (is_x) {
        r.face = (d.x > 0.f) ? 0 : 1;
        ma = ax;
        r.u = (d.x > 0.f) ? -d.z : d.z;
        r.v = -d.y;
    } else if (is_y) {
        r.face = (d.y > 0.f) ? 2 : 3;
        ma = ay;
        r.u = d.x;
        r.v = (d.y > 0.f) ? d.z : -d.z;
    } else {
        r.face = (d.z > 0.f) ? 4 : 5;
        ma = az;
        r.u = d.x * ((d.z > 0.f) ? 1.f : -1.f);
        r.v = -d.y;
    }
    float inv_ma = 1.f / fmaxf(ma, 1e-20f);
    r.u *= inv_ma; r.v *= inv_ma;
    return r;
}

struct BilinXY { int x0, x1, y0, y1; float w00, w01, w10, w11; };

__device__ __forceinline__ BilinXY bilin_xy(int R, CubeUV cu) {
    float fu = fmaf(cu.u, 0.5f * (float)R, 0.5f * (float)R - 0.5f);
    float fv = fmaf(cu.v, 0.5f * (float)R, 0.5f * (float)R - 0.5f);
    float x0f = floorf(fu), y0f = floorf(fv);
    float tx = fu - x0f, ty = fv - y0f;
    BilinXY b;
    b.x0 = min(max((int)x0f, 0), R - 1);
    b.x1 = min(b.x0 + 1, R - 1);
    b.y0 = min(max((int)y0f, 0), R - 1);
    b.y1 = min(b.y0 + 1, R - 1);
    b.w00 = (1.f - tx) * (1.f - ty);
    b.w01 = tx * (1.f - ty);
    b.w10 = (1.f - tx) * ty;
    b.w11 = tx * ty;
    return b;
}

__device__ __forceinline__ F3 blend4(float4 c00, float4 c01, float4 c10, float4 c11,
                                     float w00, float w01, float w10, float w11) {
    return f3(c00.x*w00 + c01.x*w01 + c10.x*w10 + c11.x*w11,
              c00.y*w00 + c01.y*w01 + c10.y*w10 + c11.y*w11,
              c00.z*w00 + c01.z*w01 + c10.z*w10 + c11.z*w11);
}

// Convert the two half4 texels inside a uint4 pair.
__device__ __forceinline__ float4 pair_lo(uint4 q) {
    float2 a = __half22float2(*(const __half2*)&q.x);
    float2 b = __half22float2(*(const __half2*)&q.y);
    return make_float4(a.x, a.y, b.x, 0.f);
}
__device__ __forceinline__ float4 pair_hi(uint4 q) {
    float2 a = __half22float2(*(const __half2*)&q.z);
    float2 b = __half22float2(*(const __half2*)&q.w);
    return make_float4(a.x, a.y, b.x, 0.f);
}

// Bilinear from dual-copy half4 global storage (mips 0-3): 2 x LDG.128.
__device__ __forceinline__ F3 bilerp_pair_global(int off, int R, CubeUV cu) {
    BilinXY b = bilin_xy(R, cu);
    int rowbase = off + cu.face * R * R;
    int i0 = rowbase + b.y0 * R + b.x0;
    int i1 = rowbase + b.y1 * R + b.x0;
    const uint4* base = (b.x0 & 1) ? g_mipB : g_mipA;
    uint4 q0 = __ldg(base + (i0 >> 1));
    uint4 q1 = __ldg(base + (i1 >> 1));
    if (b.x1 == b.x0) { q0.z = q0.x; q0.w = q0.y; q1.z = q1.x; q1.w = q1.y; }
    return blend4(pair_lo(q0), pair_hi(q0), pair_lo(q1), pair_hi(q1),
                  b.w00, b.w01, b.w10, b.w11);
}

__device__ __forceinline__ F3 bilerp_smem_f4(const float4* __restrict__ s, int R, CubeUV cu) {
    BilinXY b = bilin_xy(R, cu);
    int base = cu.face * R * R;
    return blend4(s[base + b.y0*R + b.x0], s[base + b.y0*R + b.x1],
                  s[base + b.y1*R + b.x0], s[base + b.y1*R + b.x1],
                  b.w00, b.w01, b.w10, b.w11);
}

__device__ __forceinline__ float4 h4_to_f4(ushort4 u) {
    return make_float4(__half2float(__ushort_as_half(u.x)),
                       __half2float(__ushort_as_half(u.y)),
                       __half2float(__ushort_as_half(u.z)), 0.f);
}

__device__ __forceinline__ F3 bilerp_smem_h4(const ushort4* __restrict__ s, int R, CubeUV cu) {
    BilinXY b = bilin_xy(R, cu);
    int base = cu.face * R * R;
    return blend4(h4_to_f4(s[base + b.y0*R + b.x0]), h4_to_f4(s[base + b.y0*R + b.x1]),
                  h4_to_f4(s[base + b.y1*R + b.x0]), h4_to_f4(s[base + b.y1*R + b.x1]),
                  b.w00, b.w01, b.w10, b.w11);
}

__device__ __forceinline__ F3 sample_spec_level(int l, CubeUV cu,
                                                const float4* __restrict__ s_mip5,
                                                const ushort4* __restrict__ s_mip4) {
    if (l <= 3) return bilerp_pair_global(c_spec_off[l], c_spec_res[l], cu);
    if (l == 4) return bilerp_smem_h4(s_mip4, 32, cu);
    return bilerp_smem_f4(s_mip5, 16, cu);
}

__device__ __forceinline__ float srgb1(float x) {
    float lin = 12.92f * x;
    float xa = fmaxf(x, 0.0031308f);
    float g = 1.055f * exp2f(__log2f(xa) * (1.0f / 2.4f)) - 0.055f;
    return (x <= 0.0031308f) ? lin : g;
}

__device__ __forceinline__ ushort4 f4_to_h4(float4 v) {
    return make_ushort4(__half_as_ushort(__float2half_rn(v.x)),
                        __half_as_ushort(__float2half_rn(v.y)),
                        __half_as_ushort(__float2half_rn(v.z)), 0);
}

#define THREADS 256
#define GRIDB   304   // 2 blocks per SM on GB300 (152 SMs)

__global__ __launch_bounds__(THREADS, 2)
void envlight_kernel(
    const float* __restrict__ view_dir,
    const float* __restrict__ normal,
    const float* __restrict__ kd,
    const float* __restrict__ ks,
    const float* __restrict__ reflect_occ,
    float* __restrict__ out,
    int ngroups)
{
    extern __shared__ unsigned char smem_raw[];
    float4*  s_diff = (float4*)smem_raw;                 // 1536 * 16B = 24KB
    float4*  s_mip5 = s_diff + 1536;                     // 1536 * 16B = 24KB
    ushort4* s_mip4 = (ushort4*)(s_mip5 + 1536);         // 6144 *  8B = 48KB

    for (int i = threadIdx.x; i < 1536; i += THREADS) {
        s_mip5[i] = g_small[6144 + i];
        s_diff[i] = g_small[7680 + i];
    }
    for (int i = threadIdx.x; i < 6144; i += THREADS) {
        s_mip4[i] = f4_to_h4(g_small[i]);
    }
    __syncthreads();

    for (int t = blockIdx.x * THREADS + threadIdx.x; t < ngroups; t += GRIDB * THREADS) {
        const float4* v4  = (const float4*)view_dir   + 3 * (size_t)t;
        const float4* n4  = (const float4*)normal     + 3 * (size_t)t;
        const float4* kd4 = (const float4*)kd         + 3 * (size_t)t;
        const float4* ks4 = (const float4*)ks         + 3 * (size_t)t;

        float vv[12], nn[12], dd[12], ss[12], oo[12];
        {
            float4 a = __ldg(v4), b = __ldg(v4 + 1), c = __ldg(v4 + 2);
            vv[0]=a.x; vv[1]=a.y; vv[2]=a.z; vv[3]=a.w; vv[4]=b.x; vv[5]=b.y;
            vv[6]=b.z; vv[7]=b.w; vv[8]=c.x; vv[9]=c.y; vv[10]=c.z; vv[11]=c.w;
        }
        {
            float4 a = __ldg(n4), b = __ldg(n4 + 1), c = __ldg(n4 + 2);
            nn[0]=a.x; nn[1]=a.y; nn[2]=a.z; nn[3]=a.w; nn[4]=b.x; nn[5]=b.y;
            nn[6]=b.z; nn[7]=b.w; nn[8]=c.x; nn[9]=c.y; nn[10]=c.z; nn[11]=c.w;
        }
        {
            float4 a = __ldg(kd4), b = __ldg(kd4 + 1), c = __ldg(kd4 + 2);
            dd[0]=a.x; dd[1]=a.y; dd[2]=a.z; dd[3]=a.w; dd[4]=b.x; dd[5]=b.y;
            dd[6]=b.z; dd[7]=b.w; dd[8]=c.x; dd[9]=c.y; dd[10]=c.z; dd[11]=c.w;
        }
        {
            float4 a = __ldg(ks4), b = __ldg(ks4 + 1), c = __ldg(ks4 + 2);
            ss[0]=a.x; ss[1]=a.y; ss[2]=a.z; ss[3]=a.w; ss[4]=b.x; ss[5]=b.y;
            ss[6]=b.z; ss[7]=b.w; ss[8]=c.x; ss[9]=c.y; ss[10]=c.z; ss[11]=c.w;
        }
        float4 occ4 = __ldg((const float4*)reflect_occ + t);
        float occA[4] = {occ4.x, occ4.y, occ4.z, occ4.w};

        #pragma unroll
        for (int p = 0; p < 4; p++) {
            F3 v   = f3(vv[3*p], vv[3*p+1], vv[3*p+2]);
            F3 nrm = f3(nn[3*p], nn[3*p+1], nn[3*p+2]);
            F3 kdv = f3(dd[3*p], dd[3*p+1], dd[3*p+2]);
            float ks0 = ss[3*p], roughness = ss[3*p+1], metallic = ss[3*p+2];
            float occ = occA[p];

            F3 spec_col = f3((1.f - metallic) * 0.04f + kdv.x * metallic,
                             (1.f - metallic) * 0.04f + kdv.y * metallic,
                             (1.f - metallic) * 0.04f + kdv.z * metallic);
            F3 diff_col = f3(kdv.x * (1.f - metallic), kdv.y * (1.f - metallic), kdv.z * (1.f - metallic));

            float vdotn = v.x * nrm.x + v.y * nrm.y + v.z * nrm.z;
            F3 refl = f3(2.f * vdotn * nrm.x - v.x,
                         2.f * vdotn * nrm.y - v.y,
                         2.f * vdotn * nrm.z - v.z);
            float rr = fmaxf(refl.x*refl.x + refl.y*refl.y + refl.z*refl.z, 1e-20f);
            float rinv = rsqrtf(rr);
            refl = f3(refl.x * rinv, refl.y * rinv, refl.z * rinv);

            // diffuse from smem 16^2 cubemap (float4 texels)
            CubeUV cun = cube_face_uv(nrm);
            F3 diffuse = bilerp_smem_f4(s_diff, 16, cun);
            diffuse = f3(fmaxf(diffuse.x, 0.f), fmaxf(diffuse.y, 0.f), fmaxf(diffuse.z, 0.f));
            float kdocc = 1.f - ks0;
            F3 shaded = f3(diffuse.x * diff_col.x * kdocc,
                           diffuse.y * diff_col.y * kdocc,
                           diffuse.z * diff_col.z * kdocc);

            // FG LUT 256x256x2 (half2 dual-copy pair loads: 2 x LDG.64)
            float NdotV = fmaxf(vdotn, 0.0001f);
            float fg0, fg1;
            {
                const int W = 256, H = 256;
                float fx = NdotV * W - 0.5f;
                float fy = roughness * H - 0.5f;
                float x0f = floorf(fx), y0f = floorf(fy);
                float tx = fx - x0f, ty = fy - y0f;
                int x0 = min(max((int)x0f, 0), W - 1);
                int x1 = min(x0 + 1, W - 1);
                int y0 = min(max((int)y0f, 0), H - 1);
                int y1 = min(y0 + 1, H - 1);
                int k0 = y0 * W + x0;
                int k1 = y1 * W + x0;
                const uint2* lbase = (x0 & 1) ? g_lutB : g_lutA;
                uint2 q0 = __ldg(lbase + (k0 >> 1));
                uint2 q1 = __ldg(lbase + (k1 >> 1));
                if (x1 == x0) { q0.y = q0.x; q1.y = q1.x; }
                float2 c00 = __half22float2(*(const __half2*)&q0.x);
                float2 c01 = __half22float2(*(const __half2*)&q0.y);
                float2 c10 = __half22float2(*(const __half2*)&q1.x);
                float2 c11 = __half22float2(*(const __half2*)&q1.y);
                float w00 = (1.f - tx) * (1.f - ty);
                float w01 = tx * (1.f - ty);
                float w10 = (1.f - tx) * ty;
                float w11 = tx * ty;
                fg0 = c00.x*w00 + c01.x*w01 + c10.x*w10 + c11.x*w11;
                fg1 = c00.y*w00 + c01.y*w01 + c10.y*w10 + c11.y*w11;
            }

            // mip level selection
            const float MIN_R = 0.08f, MAX_R = 0.5f;
            const int L = 6;
            float rc_lo = fminf(fmaxf(roughness, MIN_R), MAX_R);
            float lo = (rc_lo - MIN_R) * ((float)(L - 2) / (MAX_R - MIN_R));
            float rc_hi = fminf(fmaxf(roughness, MAX_R), 1.0f);
            float hi = (rc_hi - MAX_R) * (1.0f / (1.0f - MAX_R)) + (float)(L - 2);
            float lvl = (roughness < MAX_R) ? lo : hi;
            lvl = fminf(fmaxf(lvl, 0.f), (float)(L - 1));
            int l0 = (int)floorf(lvl);
            int l1 = min(l0 + 1, L - 1);
            float lf = lvl - (float)l0;

            CubeUV cur = cube_face_uv(refl);
            F3 s0 = sample_spec_level(l0, cur, s_mip5, s_mip4);
            F3 s1 = sample_spec_level(l1, cur, s_mip5, s_mip4);
            F3 spec = f3(s0.x * (1.f - lf) + s1.x * lf,
                         s0.y * (1.f - lf) + s1.y * lf,
                         s0.z * (1.f - lf) + s1.z * lf);
            spec = f3(fmaxf(spec.x, 0.f), fmaxf(spec.y, 0.f), fmaxf(spec.z, 0.f));

            float so = 1.f - occ;
            float rx = spec_col.x * fg0 + fg1;
            float ry = spec_col.y * fg0 + fg1;
            float rz = spec_col.z * fg0 + fg1;
            oo[3*p]   = srgb1(fminf(fmaxf(shaded.x + spec.x * rx * so, 0.f), 1.f));
            oo[3*p+1] = srgb1(fminf(fmaxf(shaded.y + spec.y * ry * so, 0.f), 1.f));
            oo[3*p+2] = srgb1(fminf(fmaxf(shaded.z + spec.z * rz * so, 0.f), 1.f));
        }

        float4* o4 = (float4*)out + 3 * (size_t)t;
        o4[0] = make_float4(oo[0], oo[1], oo[2], oo[3]);
        o4[1] = make_float4(oo[4], oo[5], oo[6], oo[7]);
        o4[2] = make_float4(oo[8], oo[9], oo[10], oo[11]);
    }
}

#define SMEM_BYTES (1536*16 + 1536*16 + 6144*8)   // 96 KB

extern "C" void kernel_launch(void* const* d_in, const int* in_sizes, int n_in,
                              void* d_out, int out_size) {
    const float* view_dir    = (const float*)d_in[0];
    const float* normal      = (const float*)d_in[1];
    const float* kd          = (const float*)d_in[2];
    const float* ks          = (const float*)d_in[3];
    const float* reflect_occ = (const float*)d_in[4];
    const float* diffuse_map = (const float*)d_in[5];
    const float* fg_lut      = (const float*)d_in[12];
    float* out = (float*)d_out;

    cudaFuncSetAttribute(envlight_kernel,
                         cudaFuncAttributeMaxDynamicSharedMemorySize, SMEM_BYTES);

    // One fused repack launch for all mips + small textures + LUT
    {
        int threads = 256;
        int blocks = (NREPACK + threads - 1) / threads;
        repack_all_kernel<<<blocks, threads>>>(
            (const float*)d_in[6], (const float*)d_in[7], (const float*)d_in[8],
            (const float*)d_in[9], (const float*)d_in[10], (const float*)d_in[11],
            diffuse_map, fg_lut);
    }

    int n = in_sizes[0] / 3;          // 2,097,152 (divisible by 4)
    int ngroups = n / 4;
    envlight_kernel<<<GRIDB, THREADS, SMEM_BYTES>>>(view_dir, normal, kd, ks, reflect_occ,
                                                    out, ngroups);
}